// round 16
// baseline (speedup 1.0000x reference)
#include <cuda_runtime.h>
#include <cuda_bf16.h>
#include <cstdint>

#define NN   20000
#define EE   320000
#define DD   300
#define LL   5
#define VV   119
#define EDIMM 7
#define GG   128
#define NCC  6
#define HH   150
#define BN_EPS 1e-5f

#define KPAD 304
#define KP   320
#define NGRP 38
#define PSTR (2*KPAD)
#define WSTR (2*KP)
#define TM   144
#define TPR  72
#define AGG_CTAS 1184

// ---------------- scratch ----------------------------------------------------
__device__ float g_h[NN * DD];
__device__ float g_P[(NN / 2) * PSTR];
__device__ float g_C[NN * DD];
__device__ float g_Wt[10 * (KP / 2) * WSTR];
__device__ float g_eattr[(size_t)EE * 8];
__device__ int   g_rowptr[NN + 1];
__device__ int   g_fill[NN];
__device__ int   g_csrc[EE];
__device__ float g_sum[DD];
__device__ float g_sumsq[DD];
__device__ float g_alpha[DD];
__device__ float g_beta[DD];
__device__ int   g_ctr;

// ---------------- helpers ----------------------------------------------------
__device__ __forceinline__ void cp_async16(uint32_t dst, const void* src, bool pred) {
    int sz = pred ? 16 : 0;
    asm volatile("cp.async.cg.shared.global [%0], [%1], 16, %2;"
                 :: "r"(dst), "l"(src), "r"(sz));
}
__device__ __forceinline__ void cp_commit() { asm volatile("cp.async.commit_group;"); }
template <int N> __device__ __forceinline__ void cp_wait() {
    asm volatile("cp.async.wait_group %0;" :: "n"(N));
}
__device__ __forceinline__ float to_tf32f(float x) {
    uint32_t r;
    asm("cvt.rna.tf32.f32 %0, %1;" : "=r"(r) : "f"(x));
    return __uint_as_float(r);
}
__device__ __forceinline__ void mma_tf32(float* d, const uint32_t* a, const uint32_t* b) {
    asm volatile(
        "mma.sync.aligned.m16n8k8.row.col.f32.tf32.tf32.f32 "
        "{%0,%1,%2,%3},{%4,%5,%6,%7},{%8,%9},{%0,%1,%2,%3};"
        : "+f"(d[0]), "+f"(d[1]), "+f"(d[2]), "+f"(d[3])
        : "r"(a[0]), "r"(a[1]), "r"(a[2]), "r"(a[3]), "r"(b[0]), "r"(b[1]));
}

// ---------------- CSR build --------------------------------------------------
__global__ void k_hist(const int* __restrict__ ei) {
    int e = blockIdx.x * blockDim.x + threadIdx.x;
    if (e < EE) atomicAdd(&g_rowptr[ei[EE + e] + 1], 1);
}
__global__ void k_scan() {
    __shared__ int s[1024];
    const int CH = 20;
    int t = threadIdx.x;
    int base = t * CH;
    int vals[CH];
    int run = 0;
#pragma unroll
    for (int i = 0; i < CH; i++) {
        int idx = base + i;
        int v = (idx <= NN) ? g_rowptr[idx] : 0;
        run += v;
        vals[i] = run;
    }
    s[t] = run;
    __syncthreads();
    for (int off = 1; off < 1024; off <<= 1) {
        int v = (t >= off) ? s[t - off] : 0;
        __syncthreads();
        s[t] += v;
        __syncthreads();
    }
    int pre = s[t] - run;
#pragma unroll
    for (int i = 0; i < CH; i++) {
        int idx = base + i;
        if (idx <= NN) {
            int rv = pre + vals[i];
            g_rowptr[idx] = rv;
            if (idx < NN) g_fill[idx] = rv;
        }
    }
}
__global__ void k_scatter(const int* __restrict__ ei, const float* __restrict__ ea) {
    int e = blockIdx.x * blockDim.x + threadIdx.x;
    if (e < EE) {
        int src = ei[e];
        int dst = ei[EE + e];
        int pos = atomicAdd(&g_fill[dst], 1);
        g_csrc[pos] = src;
        const float* a = ea + (size_t)e * EDIMM;
        float4 v0 = make_float4(a[0], a[1], a[2], a[3]);
        float4 v1 = make_float4(a[4], a[5], a[6], 0.f);
        float4* o = (float4*)(g_eattr + (size_t)pos * 8);
        o[0] = v0;
        o[1] = v1;
    }
}

// ---------------- node encoder (+ rowptr/stats/ctr zero) ---------------------
__global__ void k_encode(const int* __restrict__ x, const float* __restrict__ emb) {
    int idx = blockIdx.x * blockDim.x + threadIdx.x;
    if (idx <= NN) g_rowptr[idx] = 0;
    if (idx < DD) { g_sum[idx] = 0.f; g_sumsq[idx] = 0.f; }
    if (idx == 0) g_ctr = 0;
    if (idx < NN * (DD / 4)) {
        int n = idx / (DD / 4);
        int q = idx - n * (DD / 4);
        ((float4*)g_h)[idx] = ((const float4*)(emb + (size_t)x[n] * DD))[q];
    }
}

// ---------------- weight prep ------------------------------------------------
__global__ void k_twist(const float* __restrict__ W1, const float* __restrict__ W2) {
    int s = blockIdx.y;
    const float* W = (s < LL) ? (W1 + s * DD * DD) : (W2 + (s - LL) * DD * DD);
    int idx = blockIdx.x * blockDim.x + threadIdx.x;
    if (idx < KP * KP) {
        int n = idx / KP, ks = idx - n * KP;
        int j = ks & 7;
        int kl = (ks & ~7) | ((j & 1) ? 4 + (j >> 1) : (j >> 1));
        float v = (n < DD && kl < DD) ? to_tf32f(W[kl * DD + n]) : 0.f;
        int pairN = 8 * (n >> 4) + (n & 7);
        int jj = (n >> 3) & 1;
        g_Wt[(size_t)s * (KP / 2) * WSTR + (size_t)pairN * WSTR + ks * 2 + jj] = v;
    }
}

// ---------------- GINE aggregation (persistent, scalar, hi-occupancy) --------
__global__ void __launch_bounds__(128) k_aggregate(
    const float* __restrict__ edge_W,
    const float* __restrict__ edge_b,
    const float* __restrict__ eps, int layer,
    float* __restrict__ zout)
{
    int tid = threadIdx.x;
    int warp = tid >> 5, lane = tid & 31;

    float wreg[10][EDIMM];
    float ebr[10];
#pragma unroll
    for (int j = 0; j < 10; j++) {
        int d = lane + 32 * j;
        if (d < DD) {
            ebr[j] = edge_b[d];
#pragma unroll
            for (int k = 0; k < EDIMM; k++) wreg[j][k] = edge_W[k * DD + d];
        } else {
            ebr[j] = 0.f;
#pragma unroll
            for (int k = 0; k < EDIMM; k++) wreg[j][k] = 0.f;
        }
    }
    float epsv = 1.f + eps[layer];
    int lane_off = 2 * (lane & 3) + ((lane >> 2) & 1);
    int lane_hi = lane & 24;

    for (int node = blockIdx.x * 4 + warp; node < NN; node += AGG_CTAS * 4) {
        float acc[10];
#pragma unroll
        for (int j = 0; j < 10; j++) acc[j] = 0.f;

        int beg = g_rowptr[node], end = g_rowptr[node + 1];
#pragma unroll 2
        for (int idx = beg; idx < end; idx++) {
            int src = g_csrc[idx];
            const float4* ea4 = (const float4*)(g_eattr + (size_t)idx * 8);
            float4 x0 = ea4[0];
            float4 x1 = ea4[1];
            float a[EDIMM] = {x0.x, x0.y, x0.z, x0.w, x1.x, x1.y, x1.z};
            const float* hrow = g_h + (size_t)src * DD;
#pragma unroll
            for (int j = 0; j < 10; j++) {
                int d = lane + 32 * j;
                if (d < DD) {
                    float ea = ebr[j];
#pragma unroll
                    for (int k = 0; k < EDIMM; k++) ea = fmaf(a[k], wreg[j][k], ea);
                    acc[j] += fmaxf(hrow[d] + ea, 0.f);
                }
            }
        }

        size_t base = (size_t)(8 * (node >> 4) + (node & 7)) * PSTR + ((node >> 3) & 1);
#pragma unroll
        for (int j = 0; j < 10; j++) {
            int d = lane + 32 * j;
            if (d < DD) {
                float v = to_tf32f(epsv * g_h[(size_t)node * DD + d] + acc[j]);
                zout[base + (size_t)(32 * j + lane_hi + lane_off) * 2] = v;
            }
        }
        if (lane < 4) zout[base + (size_t)(297 + 2 * lane) * 2] = 0.f;
    }
}

// ---------------- tf32 mma.sync GEMM + fused BN stats + last-CTA finstats ----
#define NS 4

__global__ void __launch_bounds__(192, 2) k_gemm_tc(
    const float* __restrict__ A,
    const float* __restrict__ Bt,
    const float* __restrict__ bias,
    const float* __restrict__ gam, const float* __restrict__ bet,
    float* __restrict__ C, int M)
{
    __shared__ float As[NS][TPR * 16];
    __shared__ float Bs[NS][80 * 16];
    __shared__ float s_sum[160], s_ssq[160];
    __shared__ int s_last;

    int t = threadIdx.x;
    int warp = t >> 5, lane = t & 31;
    int g = lane >> 2, tq = lane & 3;
    int m0 = blockIdx.y * TM;
    int n0 = blockIdx.x * 160;
    int wm = (warp >> 1) * 48;
    int wn = (warp & 1) * 80;

    if (t < 160) { s_sum[t] = 0.f; s_ssq[t] = 0.f; }

    uint32_t asb = (uint32_t)__cvta_generic_to_shared(&As[0][0]);
    uint32_t bsb = (uint32_t)__cvta_generic_to_shared(&Bs[0][0]);

    int pairBase = blockIdx.y * TPR;
    int bprB = (n0 >> 4) * 8;

    auto issue = [&](int s, int it) {
#pragma unroll
        for (int i = 0; i < 2; i++) {
            int q = t + 192 * i;
            if (q < 288) {
                int pr = q >> 2, ck = q & 3;
                int gp = pairBase + pr;
                int u = 16 * (gp >> 3) + (gp & 7);
                cp_async16(asb + (s * TPR * 16 + pr * 16 + ck * 4) * 4,
                           A + (size_t)gp * PSTR + it * 16 + ck * 4, u < M);
            }
        }
#pragma unroll
        for (int i = 0; i < 2; i++) {
            int q = t + 192 * i;
            if (q < 320) {
                int pr = q >> 2, ck = q & 3;
                cp_async16(bsb + (s * 1280 + pr * 16 + ck * 4) * 4,
                           Bt + (size_t)(bprB + pr) * WSTR + it * 16 + ck * 4, true);
            }
        }
        cp_commit();
    };

    float c[3][10][4];
#pragma unroll
    for (int i = 0; i < 3; i++)
#pragma unroll
        for (int j = 0; j < 10; j++)
#pragma unroll
            for (int q = 0; q < 4; q++) c[i][j][q] = 0.f;

    issue(0, 0);
    issue(1, 1);
    issue(2, 2);

    for (int it = 0; it < NGRP; it++) {
        cp_wait<NS - 2>();
        __syncthreads();

        int pre = it + NS - 1;
        if (pre < NGRP) issue(pre % NS, pre);
        else cp_commit();

        const float* Af = As[it % NS];
        const float* Bf = Bs[it % NS];

        uint32_t af[3][4];
#pragma unroll
        for (int fm = 0; fm < 3; fm++) {
            int pr = (3 * (warp >> 1) + fm) * 8 + g;
            float4 fa = *(const float4*)&Af[pr * 16 + 4 * tq];
            af[fm][0] = __float_as_uint(fa.x);
            af[fm][1] = __float_as_uint(fa.y);
            af[fm][2] = __float_as_uint(fa.z);
            af[fm][3] = __float_as_uint(fa.w);
        }
#pragma unroll
        for (int fp = 0; fp < 5; fp++) {
            int pr = (wn >> 1) + fp * 8 + g;
            float4 fb = *(const float4*)&Bf[pr * 16 + 4 * tq];
            uint32_t b0[2] = {__float_as_uint(fb.x), __float_as_uint(fb.z)};
            uint32_t b1[2] = {__float_as_uint(fb.y), __float_as_uint(fb.w)};
#pragma unroll
            for (int fm = 0; fm < 3; fm++) {
                mma_tf32(c[fm][2 * fp],     af[fm], b0);
                mma_tf32(c[fm][2 * fp + 1], af[fm], b1);
            }
        }
    }

    // ---- epilogue: bias + store + BN stats ----
#pragma unroll
    for (int fm = 0; fm < 3; fm++) {
        int r0 = m0 + wm + fm * 16 + g;
        int r1 = r0 + 8;
        bool v0 = r0 < M, v1 = r1 < M;
#pragma unroll
        for (int fn = 0; fn < 10; fn++) {
            int col = n0 + wn + fn * 8 + tq * 2;
            bool cv = col < DD;
            float bx = 0.f, by = 0.f;
            if (cv) { bx = bias[col]; by = bias[col + 1]; }
            float c00 = c[fm][fn][0] + bx, c01 = c[fm][fn][1] + by;
            float c10 = c[fm][fn][2] + bx, c11 = c[fm][fn][3] + by;
            if (cv && v0) *(float2*)&C[(size_t)r0 * DD + col] = make_float2(c00, c01);
            if (cv && v1) *(float2*)&C[(size_t)r1 * DD + col] = make_float2(c10, c11);

            float s0 = (v0 ? c00 : 0.f) + (v1 ? c10 : 0.f);
            float q0 = (v0 ? c00 * c00 : 0.f) + (v1 ? c10 * c10 : 0.f);
            float s1 = (v0 ? c01 : 0.f) + (v1 ? c11 : 0.f);
            float q1 = (v0 ? c01 * c01 : 0.f) + (v1 ? c11 * c11 : 0.f);
#pragma unroll
            for (int msk = 4; msk <= 16; msk <<= 1) {
                s0 += __shfl_xor_sync(0xffffffffu, s0, msk);
                q0 += __shfl_xor_sync(0xffffffffu, q0, msk);
                s1 += __shfl_xor_sync(0xffffffffu, s1, msk);
                q1 += __shfl_xor_sync(0xffffffffu, q1, msk);
            }
            if (g == 0 && cv) {
                int si = wn + fn * 8 + tq * 2;
                atomicAdd(&s_sum[si], s0);
                atomicAdd(&s_ssq[si], q0);
                atomicAdd(&s_sum[si + 1], s1);
                atomicAdd(&s_ssq[si + 1], q1);
            }
        }
    }
    __syncthreads();
    if (t < 160) {
        int col = n0 + t;
        if (col < DD) {
            atomicAdd(&g_sum[col], s_sum[t]);
            atomicAdd(&g_sumsq[col], s_ssq[t]);
        }
    }
    __syncthreads();

    // ---- last-CTA finstats ----
    if (t == 0) {
        __threadfence();
        int total = gridDim.x * gridDim.y;
        int old = atomicAdd(&g_ctr, 1);
        s_last = (old == total - 1) ? 1 : 0;
    }
    __syncthreads();
    if (s_last) {
        const float invN = 1.f / (float)NN;
        for (int cc = t; cc < DD; cc += 192) {
            float mean = g_sum[cc] * invN;
            float var = g_sumsq[cc] * invN - mean * mean;
            float a = rsqrtf(var + BN_EPS) * gam[cc];
            g_alpha[cc] = a;
            g_beta[cc] = bet[cc] - mean * a;
            g_sum[cc] = 0.f;
            g_sumsq[cc] = 0.f;
        }
        if (t == 0) g_ctr = 0;
    }
}

// ---------------- normA (C -> P with norm, perm, pair-interleave) ------------
__global__ void k_normA(const float* __restrict__ X, float* __restrict__ P) {
    int t = blockIdx.x * blockDim.x + threadIdx.x;
    if (t >= (NN / 2) * NGRP) return;
    int pr = t / NGRP, gix = t - pr * NGRP;
    int k0 = gix * 8;
    int u = 16 * (pr >> 3) + (pr & 7);
    int v = u + 8;
    const float* xu = X + (size_t)u * DD + k0;
    const float* xv = X + (size_t)v * DD + k0;
    float* o = P + (size_t)pr * PSTR + gix * 16;
    if (gix < 37) {
        float4 a = *(const float4*)xu;
        float4 b = *(const float4*)(xu + 4);
        float4 c = *(const float4*)xv;
        float4 d = *(const float4*)(xv + 4);
        float lu[8] = {a.x, a.y, a.z, a.w, b.x, b.y, b.z, b.w};
        float lv[8] = {c.x, c.y, c.z, c.w, d.x, d.y, d.z, d.w};
#pragma unroll
        for (int i = 0; i < 8; i++) {
            float al = g_alpha[k0 + i], be = g_beta[k0 + i];
            lu[i] = to_tf32f(fmaxf(fmaf(lu[i], al, be), 0.f));
            lv[i] = to_tf32f(fmaxf(fmaf(lv[i], al, be), 0.f));
        }
        *(float4*)(o)      = make_float4(lu[0], lv[0], lu[4], lv[4]);
        *(float4*)(o + 4)  = make_float4(lu[1], lv[1], lu[5], lv[5]);
        *(float4*)(o + 8)  = make_float4(lu[2], lv[2], lu[6], lv[6]);
        *(float4*)(o + 12) = make_float4(lu[3], lv[3], lu[7], lv[7]);
    } else {
        float4 a = *(const float4*)xu;
        float4 c = *(const float4*)xv;
        float lu[4] = {a.x, a.y, a.z, a.w};
        float lv[4] = {c.x, c.y, c.z, c.w};
#pragma unroll
        for (int i = 0; i < 4; i++) {
            float al = g_alpha[k0 + i], be = g_beta[k0 + i];
            lu[i] = to_tf32f(fmaxf(fmaf(lu[i], al, be), 0.f));
            lv[i] = to_tf32f(fmaxf(fmaf(lv[i], al, be), 0.f));
        }
        *(float4*)(o)      = make_float4(lu[0], lv[0], 0.f, 0.f);
        *(float4*)(o + 4)  = make_float4(lu[1], lv[1], 0.f, 0.f);
        *(float4*)(o + 8)  = make_float4(lu[2], lv[2], 0.f, 0.f);
        *(float4*)(o + 12) = make_float4(lu[3], lv[3], 0.f, 0.f);
    }
}
// ---------------- normH (C -> h, fp32 normal layout) -------------------------
__global__ void k_normH(const float* __restrict__ X, float* __restrict__ Y) {
    int idx = blockIdx.x * blockDim.x + threadIdx.x;
    if (idx < NN * (DD / 4)) {
        float4 x = ((const float4*)X)[idx];
        int c4 = (idx % (DD / 4)) * 4;
        float4 y;
        y.x = fmaxf(fmaf(x.x, g_alpha[c4],     g_beta[c4]),     0.f);
        y.y = fmaxf(fmaf(x.y, g_alpha[c4 + 1], g_beta[c4 + 1]), 0.f);
        y.z = fmaxf(fmaf(x.z, g_alpha[c4 + 2], g_beta[c4 + 2]), 0.f);
        y.w = fmaxf(fmaf(x.w, g_alpha[c4 + 3], g_beta[c4 + 3]), 0.f);
        ((float4*)Y)[idx] = y;
    }
}

// ---------------- fused final norm + pool + classifier -----------------------
__global__ void __launch_bounds__(320) k_poolclass(
    const int* __restrict__ batch, const float* __restrict__ X,
    const float* __restrict__ Wc1, const float* __restrict__ bc1,
    const float* __restrict__ Wc2, const float* __restrict__ bc2,
    float* __restrict__ out)
{
    __shared__ int sb[2];
    __shared__ float p[DD];
    __shared__ float hid[HH];
    int g = blockIdx.x, t = threadIdx.x;
    if (t < 2) {
        int target = g + t;
        int lo = 0, hi = NN;
        while (lo < hi) {
            int mid = (lo + hi) >> 1;
            if (batch[mid] < target) lo = mid + 1; else hi = mid;
        }
        sb[t] = lo;
    }
    __syncthreads();
    int s = sb[0], e = sb[1];
    if (t < DD) {
        float al = g_alpha[t], be = g_beta[t];
        float acc = 0.f;
        for (int r = s; r < e; r++)
            acc += fmaxf(fmaf(X[(size_t)r * DD + t], al, be), 0.f);
        p[t] = acc / fmaxf((float)(e - s), 1.f);
    }
    __syncthreads();
    if (t < HH) {
        float sum = bc1[t];
        for (int k = 0; k < DD; k++) sum = fmaf(p[k], Wc1[k * HH + t], sum);
        hid[t] = fmaxf(sum, 0.f);
    }
    __syncthreads();
    if (t < NCC) {
        float sum = bc2[t];
        for (int k = 0; k < HH; k++) sum = fmaf(hid[k], Wc2[k * NCC + t], sum);
        out[g * NCC + t] = sum;
    }
}

// ---------------- launch -----------------------------------------------------
extern "C" void kernel_launch(void* const* d_in, const int* in_sizes, int n_in,
                              void* d_out, int out_size)
{
    const int*   x  = (const int*)d_in[0];
    const int*   ei = (const int*)d_in[1];
    const float* edge_attr;
    const int*   batch;
    if (in_sizes[2] == EE * EDIMM) {
        edge_attr = (const float*)d_in[2];
        batch     = (const int*)d_in[3];
    } else {
        batch     = (const int*)d_in[2];
        edge_attr = (const float*)d_in[3];
    }
    const float* node_emb = (const float*)d_in[4];
    const float* edge_W   = (const float*)d_in[5];
    const float* edge_b   = (const float*)d_in[6];
    const float* eps      = (const float*)d_in[7];
    const float* W1  = (const float*)d_in[8];
    const float* b1  = (const float*)d_in[9];
    const float* g1  = (const float*)d_in[10];
    const float* be1 = (const float*)d_in[11];
    const float* W2  = (const float*)d_in[12];
    const float* b2  = (const float*)d_in[13];
    const float* g2  = (const float*)d_in[14];
    const float* be2 = (const float*)d_in[15];
    const float* Wc1 = (const float*)d_in[16];
    const float* bc1 = (const float*)d_in[17];
    const float* Wc2 = (const float*)d_in[18];
    const float* bc2 = (const float*)d_in[19];
    float* out = (float*)d_out;

    float *p_h, *p_P, *p_C, *p_Wt;
    cudaGetSymbolAddress((void**)&p_h, g_h);
    cudaGetSymbolAddress((void**)&p_P, g_P);
    cudaGetSymbolAddress((void**)&p_C, g_C);
    cudaGetSymbolAddress((void**)&p_Wt, g_Wt);

    const int NE_BLOCKS = (NN * (DD / 4) + 255) / 256;
    const int NA_BLOCKS = ((NN / 2) * NGRP + 255) / 256;
    const size_t WMAT = (size_t)(KP / 2) * WSTR;

    // encoder (zeroes rowptr + BN stats + counter) + weight prep, then CSR
    k_encode<<<NE_BLOCKS, 256>>>(x, node_emb);
    {
        dim3 tg((KP * KP + 255) / 256, 10);
        k_twist<<<tg, 256>>>(W1, W2);
    }
    k_hist<<<(EE + 255) / 256, 256>>>(ei);
    k_scan<<<1, 1024>>>();
    k_scatter<<<(EE + 255) / 256, 256>>>(ei, edge_attr);

    dim3 ggrid(2, (NN + TM - 1) / TM);   // 278 CTAs, single wave
    for (int l = 0; l < LL; l++) {
        k_aggregate<<<AGG_CTAS, 128>>>(edge_W, edge_b, eps, l, p_P);
        k_gemm_tc<<<ggrid, 192>>>(p_P, p_Wt + (size_t)l * WMAT,
                                  b1 + l * DD, g1 + l * DD, be1 + l * DD, p_C, NN);
        k_normA<<<NA_BLOCKS, 256>>>(p_C, p_P);
        k_gemm_tc<<<ggrid, 192>>>(p_P, p_Wt + (size_t)(LL + l) * WMAT,
                                  b2 + l * DD, g2 + l * DD, be2 + l * DD, p_C, NN);
        if (l < LL - 1)
            k_normH<<<NE_BLOCKS, 256>>>(p_C, p_h);
    }

    // fused final norm + pooling + classifier
    k_poolclass<<<GG, 320>>>(batch, p_C, Wc1, bc1, Wc2, bc2, out);
}

// round 17
// speedup vs baseline: 1.0126x; 1.0126x over previous
#include <cuda_runtime.h>
#include <cuda_bf16.h>
#include <cstdint>

#define NN   20000
#define EE   320000
#define DD   300
#define LL   5
#define VV   119
#define EDIMM 7
#define GG   128
#define NCC  6
#define HH   150
#define BN_EPS 1e-5f

#define KPAD 304
#define KP   320
#define NGRP 38
#define PSTR (2*KPAD)
#define WSTR (2*KP)
#define TM   144
#define TPR  72
#define AGG_CTAS 1184

#define SCAN_ELTS 20032          // NN+1 rounded up
#define SCAN_SMEM ((SCAN_ELTS + 1024) * 4)

// ---------------- scratch ----------------------------------------------------
__device__ float g_h[NN * DD];
__device__ float g_P[(NN / 2) * PSTR];
__device__ float g_C[NN * DD];
__device__ float g_Wt[10 * (KP / 2) * WSTR];
__device__ float g_eattr[(size_t)EE * 8];
__device__ int   g_rowptr[NN + 1];
__device__ int   g_fill[NN];
__device__ int   g_csrc[EE];
__device__ float g_sum[DD];
__device__ float g_sumsq[DD];
__device__ float g_alpha[DD];
__device__ float g_beta[DD];
__device__ int   g_ctr;

// ---------------- helpers ----------------------------------------------------
__device__ __forceinline__ void cp_async16(uint32_t dst, const void* src, bool pred) {
    int sz = pred ? 16 : 0;
    asm volatile("cp.async.cg.shared.global [%0], [%1], 16, %2;"
                 :: "r"(dst), "l"(src), "r"(sz));
}
__device__ __forceinline__ void cp_commit() { asm volatile("cp.async.commit_group;"); }
template <int N> __device__ __forceinline__ void cp_wait() {
    asm volatile("cp.async.wait_group %0;" :: "n"(N));
}
__device__ __forceinline__ float to_tf32f(float x) {
    uint32_t r;
    asm("cvt.rna.tf32.f32 %0, %1;" : "=r"(r) : "f"(x));
    return __uint_as_float(r);
}
__device__ __forceinline__ void mma_tf32(float* d, const uint32_t* a, const uint32_t* b) {
    asm volatile(
        "mma.sync.aligned.m16n8k8.row.col.f32.tf32.tf32.f32 "
        "{%0,%1,%2,%3},{%4,%5,%6,%7},{%8,%9},{%0,%1,%2,%3};"
        : "+f"(d[0]), "+f"(d[1]), "+f"(d[2]), "+f"(d[3])
        : "r"(a[0]), "r"(a[1]), "r"(a[2]), "r"(a[3]), "r"(b[0]), "r"(b[1]));
}

// ---------------- CSR build --------------------------------------------------
__global__ void k_hist(const int* __restrict__ ei) {
    int e = blockIdx.x * blockDim.x + threadIdx.x;
    if (e < EE) atomicAdd(&g_rowptr[ei[EE + e] + 1], 1);
}
// smem-staged inclusive scan over g_rowptr[0..NN]; seeds g_fill.
__global__ void k_scan() {
    extern __shared__ int s[];           // [0, SCAN_ELTS): data; [SCAN_ELTS,+1024): block sums
    int* bs = s + SCAN_ELTS;
    int t = threadIdx.x;

    // coalesced load
    for (int i = t; i <= NN; i += 1024) s[i] = g_rowptr[i];
    __syncthreads();

    const int CH = 20;
    int base = t * CH;
    int vals[CH];
    int run = 0;
#pragma unroll
    for (int i = 0; i < CH; i++) {
        int idx = base + i;
        int v = (idx <= NN) ? s[idx] : 0;
        run += v;
        vals[i] = run;
    }
    bs[t] = run;
    __syncthreads();
    for (int off = 1; off < 1024; off <<= 1) {
        int v = (t >= off) ? bs[t - off] : 0;
        __syncthreads();
        bs[t] += v;
        __syncthreads();
    }
    int pre = bs[t] - run;
#pragma unroll
    for (int i = 0; i < CH; i++) {
        int idx = base + i;
        if (idx <= NN) s[idx] = pre + vals[i];
    }
    __syncthreads();

    // coalesced store
    for (int i = t; i <= NN; i += 1024) {
        int rv = s[i];
        g_rowptr[i] = rv;
        if (i < NN) g_fill[i] = rv;
    }
}
__global__ void k_scatter(const int* __restrict__ ei, const float* __restrict__ ea) {
    int e = blockIdx.x * blockDim.x + threadIdx.x;
    if (e < EE) {
        int src = ei[e];
        int dst = ei[EE + e];
        int pos = atomicAdd(&g_fill[dst], 1);
        g_csrc[pos] = src;
        const float* a = ea + (size_t)e * EDIMM;
        float4 v0 = make_float4(a[0], a[1], a[2], a[3]);
        float4 v1 = make_float4(a[4], a[5], a[6], 0.f);
        float4* o = (float4*)(g_eattr + (size_t)pos * 8);
        o[0] = v0;
        o[1] = v1;
    }
}

// ---------------- node encoder (+ rowptr/stats/ctr zero) ---------------------
__global__ void k_encode(const int* __restrict__ x, const float* __restrict__ emb) {
    int idx = blockIdx.x * blockDim.x + threadIdx.x;
    if (idx <= NN) g_rowptr[idx] = 0;
    if (idx < DD) { g_sum[idx] = 0.f; g_sumsq[idx] = 0.f; }
    if (idx == 0) g_ctr = 0;
    if (idx < NN * (DD / 4)) {
        int n = idx / (DD / 4);
        int q = idx - n * (DD / 4);
        ((float4*)g_h)[idx] = ((const float4*)(emb + (size_t)x[n] * DD))[q];
    }
}

// ---------------- weight prep ------------------------------------------------
__global__ void k_twist(const float* __restrict__ W1, const float* __restrict__ W2) {
    int s = blockIdx.y;
    const float* W = (s < LL) ? (W1 + s * DD * DD) : (W2 + (s - LL) * DD * DD);
    int idx = blockIdx.x * blockDim.x + threadIdx.x;
    if (idx < KP * KP) {
        int n = idx / KP, ks = idx - n * KP;
        int j = ks & 7;
        int kl = (ks & ~7) | ((j & 1) ? 4 + (j >> 1) : (j >> 1));
        float v = (n < DD && kl < DD) ? to_tf32f(W[kl * DD + n]) : 0.f;
        int pairN = 8 * (n >> 4) + (n & 7);
        int jj = (n >> 3) & 1;
        g_Wt[(size_t)s * (KP / 2) * WSTR + (size_t)pairN * WSTR + ks * 2 + jj] = v;
    }
}

// ---------------- GINE aggregation (persistent, scalar, hi-occupancy) --------
__global__ void __launch_bounds__(128) k_aggregate(
    const float* __restrict__ edge_W,
    const float* __restrict__ edge_b,
    const float* __restrict__ eps, int layer,
    float* __restrict__ zout)
{
    int tid = threadIdx.x;
    int warp = tid >> 5, lane = tid & 31;

    float wreg[10][EDIMM];
    float ebr[10];
#pragma unroll
    for (int j = 0; j < 10; j++) {
        int d = lane + 32 * j;
        if (d < DD) {
            ebr[j] = edge_b[d];
#pragma unroll
            for (int k = 0; k < EDIMM; k++) wreg[j][k] = edge_W[k * DD + d];
        } else {
            ebr[j] = 0.f;
#pragma unroll
            for (int k = 0; k < EDIMM; k++) wreg[j][k] = 0.f;
        }
    }
    float epsv = 1.f + eps[layer];
    int lane_off = 2 * (lane & 3) + ((lane >> 2) & 1);
    int lane_hi = lane & 24;

    for (int node = blockIdx.x * 4 + warp; node < NN; node += AGG_CTAS * 4) {
        float acc[10];
#pragma unroll
        for (int j = 0; j < 10; j++) acc[j] = 0.f;

        int beg = g_rowptr[node], end = g_rowptr[node + 1];
#pragma unroll 2
        for (int idx = beg; idx < end; idx++) {
            int src = g_csrc[idx];
            const float4* ea4 = (const float4*)(g_eattr + (size_t)idx * 8);
            float4 x0 = ea4[0];
            float4 x1 = ea4[1];
            float a[EDIMM] = {x0.x, x0.y, x0.z, x0.w, x1.x, x1.y, x1.z};
            const float* hrow = g_h + (size_t)src * DD;
#pragma unroll
            for (int j = 0; j < 10; j++) {
                int d = lane + 32 * j;
                if (d < DD) {
                    float ea = ebr[j];
#pragma unroll
                    for (int k = 0; k < EDIMM; k++) ea = fmaf(a[k], wreg[j][k], ea);
                    acc[j] += fmaxf(hrow[d] + ea, 0.f);
                }
            }
        }

        size_t base = (size_t)(8 * (node >> 4) + (node & 7)) * PSTR + ((node >> 3) & 1);
#pragma unroll
        for (int j = 0; j < 10; j++) {
            int d = lane + 32 * j;
            if (d < DD) {
                float v = to_tf32f(epsv * g_h[(size_t)node * DD + d] + acc[j]);
                zout[base + (size_t)(32 * j + lane_hi + lane_off) * 2] = v;
            }
        }
        if (lane < 4) zout[base + (size_t)(297 + 2 * lane) * 2] = 0.f;
    }
}

// ---------------- tf32 mma.sync GEMM + fused BN stats + last-CTA finstats ----
#define NS 4

__global__ void __launch_bounds__(192, 2) k_gemm_tc(
    const float* __restrict__ A,
    const float* __restrict__ Bt,
    const float* __restrict__ bias,
    const float* __restrict__ gam, const float* __restrict__ bet,
    float* __restrict__ C, int M)
{
    __shared__ float As[NS][TPR * 16];
    __shared__ float Bs[NS][80 * 16];
    __shared__ float s_sum[160], s_ssq[160];
    __shared__ int s_last;

    int t = threadIdx.x;
    int warp = t >> 5, lane = t & 31;
    int g = lane >> 2, tq = lane & 3;
    int m0 = blockIdx.y * TM;
    int n0 = blockIdx.x * 160;
    int wm = (warp >> 1) * 48;
    int wn = (warp & 1) * 80;

    if (t < 160) { s_sum[t] = 0.f; s_ssq[t] = 0.f; }

    uint32_t asb = (uint32_t)__cvta_generic_to_shared(&As[0][0]);
    uint32_t bsb = (uint32_t)__cvta_generic_to_shared(&Bs[0][0]);

    int pairBase = blockIdx.y * TPR;
    int bprB = (n0 >> 4) * 8;

    auto issue = [&](int s, int it) {
#pragma unroll
        for (int i = 0; i < 2; i++) {
            int q = t + 192 * i;
            if (q < 288) {
                int pr = q >> 2, ck = q & 3;
                int gp = pairBase + pr;
                int u = 16 * (gp >> 3) + (gp & 7);
                cp_async16(asb + (s * TPR * 16 + pr * 16 + ck * 4) * 4,
                           A + (size_t)gp * PSTR + it * 16 + ck * 4, u < M);
            }
        }
#pragma unroll
        for (int i = 0; i < 2; i++) {
            int q = t + 192 * i;
            if (q < 320) {
                int pr = q >> 2, ck = q & 3;
                cp_async16(bsb + (s * 1280 + pr * 16 + ck * 4) * 4,
                           Bt + (size_t)(bprB + pr) * WSTR + it * 16 + ck * 4, true);
            }
        }
        cp_commit();
    };

    float c[3][10][4];
#pragma unroll
    for (int i = 0; i < 3; i++)
#pragma unroll
        for (int j = 0; j < 10; j++)
#pragma unroll
            for (int q = 0; q < 4; q++) c[i][j][q] = 0.f;

    issue(0, 0);
    issue(1, 1);
    issue(2, 2);

    for (int it = 0; it < NGRP; it++) {
        cp_wait<NS - 2>();
        __syncthreads();

        int pre = it + NS - 1;
        if (pre < NGRP) issue(pre % NS, pre);
        else cp_commit();

        const float* Af = As[it % NS];
        const float* Bf = Bs[it % NS];

        uint32_t af[3][4];
#pragma unroll
        for (int fm = 0; fm < 3; fm++) {
            int pr = (3 * (warp >> 1) + fm) * 8 + g;
            float4 fa = *(const float4*)&Af[pr * 16 + 4 * tq];
            af[fm][0] = __float_as_uint(fa.x);
            af[fm][1] = __float_as_uint(fa.y);
            af[fm][2] = __float_as_uint(fa.z);
            af[fm][3] = __float_as_uint(fa.w);
        }
#pragma unroll
        for (int fp = 0; fp < 5; fp++) {
            int pr = (wn >> 1) + fp * 8 + g;
            float4 fb = *(const float4*)&Bf[pr * 16 + 4 * tq];
            uint32_t b0[2] = {__float_as_uint(fb.x), __float_as_uint(fb.z)};
            uint32_t b1[2] = {__float_as_uint(fb.y), __float_as_uint(fb.w)};
#pragma unroll
            for (int fm = 0; fm < 3; fm++) {
                mma_tf32(c[fm][2 * fp],     af[fm], b0);
                mma_tf32(c[fm][2 * fp + 1], af[fm], b1);
            }
        }
    }

    // ---- epilogue: bias + store + BN stats ----
#pragma unroll
    for (int fm = 0; fm < 3; fm++) {
        int r0 = m0 + wm + fm * 16 + g;
        int r1 = r0 + 8;
        bool v0 = r0 < M, v1 = r1 < M;
#pragma unroll
        for (int fn = 0; fn < 10; fn++) {
            int col = n0 + wn + fn * 8 + tq * 2;
            bool cv = col < DD;
            float bx = 0.f, by = 0.f;
            if (cv) { bx = bias[col]; by = bias[col + 1]; }
            float c00 = c[fm][fn][0] + bx, c01 = c[fm][fn][1] + by;
            float c10 = c[fm][fn][2] + bx, c11 = c[fm][fn][3] + by;
            if (cv && v0) *(float2*)&C[(size_t)r0 * DD + col] = make_float2(c00, c01);
            if (cv && v1) *(float2*)&C[(size_t)r1 * DD + col] = make_float2(c10, c11);

            float s0 = (v0 ? c00 : 0.f) + (v1 ? c10 : 0.f);
            float q0 = (v0 ? c00 * c00 : 0.f) + (v1 ? c10 * c10 : 0.f);
            float s1 = (v0 ? c01 : 0.f) + (v1 ? c11 : 0.f);
            float q1 = (v0 ? c01 * c01 : 0.f) + (v1 ? c11 * c11 : 0.f);
#pragma unroll
            for (int msk = 4; msk <= 16; msk <<= 1) {
                s0 += __shfl_xor_sync(0xffffffffu, s0, msk);
                q0 += __shfl_xor_sync(0xffffffffu, q0, msk);
                s1 += __shfl_xor_sync(0xffffffffu, s1, msk);
                q1 += __shfl_xor_sync(0xffffffffu, q1, msk);
            }
            if (g == 0 && cv) {
                int si = wn + fn * 8 + tq * 2;
                atomicAdd(&s_sum[si], s0);
                atomicAdd(&s_ssq[si], q0);
                atomicAdd(&s_sum[si + 1], s1);
                atomicAdd(&s_ssq[si + 1], q1);
            }
        }
    }
    __syncthreads();
    if (t < 160) {
        int col = n0 + t;
        if (col < DD) {
            atomicAdd(&g_sum[col], s_sum[t]);
            atomicAdd(&g_sumsq[col], s_ssq[t]);
        }
    }
    __syncthreads();

    // ---- last-CTA finstats ----
    if (t == 0) {
        __threadfence();
        int total = gridDim.x * gridDim.y;
        int old = atomicAdd(&g_ctr, 1);
        s_last = (old == total - 1) ? 1 : 0;
    }
    __syncthreads();
    if (s_last) {
        const float invN = 1.f / (float)NN;
        for (int cc = t; cc < DD; cc += 192) {
            float mean = g_sum[cc] * invN;
            float var = g_sumsq[cc] * invN - mean * mean;
            float a = rsqrtf(var + BN_EPS) * gam[cc];
            g_alpha[cc] = a;
            g_beta[cc] = bet[cc] - mean * a;
            g_sum[cc] = 0.f;
            g_sumsq[cc] = 0.f;
        }
        if (t == 0) g_ctr = 0;
    }
}

// ---------------- normA (C -> P with norm, perm, pair-interleave) ------------
__global__ void k_normA(const float* __restrict__ X, float* __restrict__ P) {
    int t = blockIdx.x * blockDim.x + threadIdx.x;
    if (t >= (NN / 2) * NGRP) return;
    int pr = t / NGRP, gix = t - pr * NGRP;
    int k0 = gix * 8;
    int u = 16 * (pr >> 3) + (pr & 7);
    int v = u + 8;
    const float* xu = X + (size_t)u * DD + k0;
    const float* xv = X + (size_t)v * DD + k0;
    float* o = P + (size_t)pr * PSTR + gix * 16;
    if (gix < 37) {
        float4 a = *(const float4*)xu;
        float4 b = *(const float4*)(xu + 4);
        float4 c = *(const float4*)xv;
        float4 d = *(const float4*)(xv + 4);
        float lu[8] = {a.x, a.y, a.z, a.w, b.x, b.y, b.z, b.w};
        float lv[8] = {c.x, c.y, c.z, c.w, d.x, d.y, d.z, d.w};
#pragma unroll
        for (int i = 0; i < 8; i++) {
            float al = g_alpha[k0 + i], be = g_beta[k0 + i];
            lu[i] = to_tf32f(fmaxf(fmaf(lu[i], al, be), 0.f));
            lv[i] = to_tf32f(fmaxf(fmaf(lv[i], al, be), 0.f));
        }
        *(float4*)(o)      = make_float4(lu[0], lv[0], lu[4], lv[4]);
        *(float4*)(o + 4)  = make_float4(lu[1], lv[1], lu[5], lv[5]);
        *(float4*)(o + 8)  = make_float4(lu[2], lv[2], lu[6], lv[6]);
        *(float4*)(o + 12) = make_float4(lu[3], lv[3], lu[7], lv[7]);
    } else {
        float4 a = *(const float4*)xu;
        float4 c = *(const float4*)xv;
        float lu[4] = {a.x, a.y, a.z, a.w};
        float lv[4] = {c.x, c.y, c.z, c.w};
#pragma unroll
        for (int i = 0; i < 4; i++) {
            float al = g_alpha[k0 + i], be = g_beta[k0 + i];
            lu[i] = to_tf32f(fmaxf(fmaf(lu[i], al, be), 0.f));
            lv[i] = to_tf32f(fmaxf(fmaf(lv[i], al, be), 0.f));
        }
        *(float4*)(o)      = make_float4(lu[0], lv[0], 0.f, 0.f);
        *(float4*)(o + 4)  = make_float4(lu[1], lv[1], 0.f, 0.f);
        *(float4*)(o + 8)  = make_float4(lu[2], lv[2], 0.f, 0.f);
        *(float4*)(o + 12) = make_float4(lu[3], lv[3], 0.f, 0.f);
    }
}
// ---------------- normH (C -> h, fp32 normal layout) -------------------------
__global__ void k_normH(const float* __restrict__ X, float* __restrict__ Y) {
    int idx = blockIdx.x * blockDim.x + threadIdx.x;
    if (idx < NN * (DD / 4)) {
        float4 x = ((const float4*)X)[idx];
        int c4 = (idx % (DD / 4)) * 4;
        float4 y;
        y.x = fmaxf(fmaf(x.x, g_alpha[c4],     g_beta[c4]),     0.f);
        y.y = fmaxf(fmaf(x.y, g_alpha[c4 + 1], g_beta[c4 + 1]), 0.f);
        y.z = fmaxf(fmaf(x.z, g_alpha[c4 + 2], g_beta[c4 + 2]), 0.f);
        y.w = fmaxf(fmaf(x.w, g_alpha[c4 + 3], g_beta[c4 + 3]), 0.f);
        ((float4*)Y)[idx] = y;
    }
}

// ---------------- fused final norm + pool + classifier -----------------------
__global__ void __launch_bounds__(320) k_poolclass(
    const int* __restrict__ batch, const float* __restrict__ X,
    const float* __restrict__ Wc1, const float* __restrict__ bc1,
    const float* __restrict__ Wc2, const float* __restrict__ bc2,
    float* __restrict__ out)
{
    __shared__ int sb[2];
    __shared__ float p[DD];
    __shared__ float hid[HH];
    int g = blockIdx.x, t = threadIdx.x;
    if (t < 2) {
        int target = g + t;
        int lo = 0, hi = NN;
        while (lo < hi) {
            int mid = (lo + hi) >> 1;
            if (batch[mid] < target) lo = mid + 1; else hi = mid;
        }
        sb[t] = lo;
    }
    __syncthreads();
    int s = sb[0], e = sb[1];
    if (t < DD) {
        float al = g_alpha[t], be = g_beta[t];
        float acc = 0.f;
        for (int r = s; r < e; r++)
            acc += fmaxf(fmaf(X[(size_t)r * DD + t], al, be), 0.f);
        p[t] = acc / fmaxf((float)(e - s), 1.f);
    }
    __syncthreads();
    if (t < HH) {
        float sum = bc1[t];
        for (int k = 0; k < DD; k++) sum = fmaf(p[k], Wc1[k * HH + t], sum);
        hid[t] = fmaxf(sum, 0.f);
    }
    __syncthreads();
    if (t < NCC) {
        float sum = bc2[t];
        for (int k = 0; k < HH; k++) sum = fmaf(hid[k], Wc2[k * NCC + t], sum);
        out[g * NCC + t] = sum;
    }
}

// ---------------- launch -----------------------------------------------------
extern "C" void kernel_launch(void* const* d_in, const int* in_sizes, int n_in,
                              void* d_out, int out_size)
{
    const int*   x  = (const int*)d_in[0];
    const int*   ei = (const int*)d_in[1];
    const float* edge_attr;
    const int*   batch;
    if (in_sizes[2] == EE * EDIMM) {
        edge_attr = (const float*)d_in[2];
        batch     = (const int*)d_in[3];
    } else {
        batch     = (const int*)d_in[2];
        edge_attr = (const float*)d_in[3];
    }
    const float* node_emb = (const float*)d_in[4];
    const float* edge_W   = (const float*)d_in[5];
    const float* edge_b   = (const float*)d_in[6];
    const float* eps      = (const float*)d_in[7];
    const float* W1  = (const float*)d_in[8];
    const float* b1  = (const float*)d_in[9];
    const float* g1  = (const float*)d_in[10];
    const float* be1 = (const float*)d_in[11];
    const float* W2  = (const float*)d_in[12];
    const float* b2  = (const float*)d_in[13];
    const float* g2  = (const float*)d_in[14];
    const float* be2 = (const float*)d_in[15];
    const float* Wc1 = (const float*)d_in[16];
    const float* bc1 = (const float*)d_in[17];
    const float* Wc2 = (const float*)d_in[18];
    const float* bc2 = (const float*)d_in[19];
    float* out = (float*)d_out;

    float *p_h, *p_P, *p_C, *p_Wt;
    cudaGetSymbolAddress((void**)&p_h, g_h);
    cudaGetSymbolAddress((void**)&p_P, g_P);
    cudaGetSymbolAddress((void**)&p_C, g_C);
    cudaGetSymbolAddress((void**)&p_Wt, g_Wt);

    cudaFuncSetAttribute(k_scan, cudaFuncAttributeMaxDynamicSharedMemorySize, SCAN_SMEM);

    const int NE_BLOCKS = (NN * (DD / 4) + 255) / 256;
    const int NA_BLOCKS = ((NN / 2) * NGRP + 255) / 256;
    const size_t WMAT = (size_t)(KP / 2) * WSTR;

    // encoder (zeroes rowptr + BN stats + counter) + weight prep, then CSR
    k_encode<<<NE_BLOCKS, 256>>>(x, node_emb);
    {
        dim3 tg((KP * KP + 255) / 256, 10);
        k_twist<<<tg, 256>>>(W1, W2);
    }
    k_hist<<<(EE + 255) / 256, 256>>>(ei);
    k_scan<<<1, 1024, SCAN_SMEM>>>();
    k_scatter<<<(EE + 255) / 256, 256>>>(ei, edge_attr);

    dim3 ggrid(2, (NN + TM - 1) / TM);   // 278 CTAs, single wave
    for (int l = 0; l < LL; l++) {
        k_aggregate<<<AGG_CTAS, 128>>>(edge_W, edge_b, eps, l, p_P);
        k_gemm_tc<<<ggrid, 192>>>(p_P, p_Wt + (size_t)l * WMAT,
                                  b1 + l * DD, g1 + l * DD, be1 + l * DD, p_C, NN);
        k_normA<<<NA_BLOCKS, 256>>>(p_C, p_P);
        k_gemm_tc<<<ggrid, 192>>>(p_P, p_Wt + (size_t)(LL + l) * WMAT,
                                  b2 + l * DD, g2 + l * DD, be2 + l * DD, p_C, NN);
        if (l < LL - 1)
            k_normH<<<NE_BLOCKS, 256>>>(p_C, p_h);
    }

    // fused final norm + pooling + classifier
    k_poolclass<<<GG, 320>>>(batch, p_C, Wc1, bc1, Wc2, bc2, out);
}